// round 10
// baseline (speedup 1.0000x reference)
#include <cuda_runtime.h>
#include <cuda.h>
#include <cuda_bf16.h>
#include <math.h>
#include <stdint.h>

// Problem constants
#define B_    2
#define Q_    75
#define WAY_  5
#define SHOT_ 5
#define HW_   100
#define C_    640
#define NK_   5

#define MROWS (Q_*HW_)        // 7500 query patches per b
#define NROWS (WAY_*HW_)      // 500 support patches per group
#define NGRP  (B_*SHOT_)      // 10 groups
#define NQTOT (B_*MROWS)      // 15000
#define NSTOT (NGRP*NROWS)    // 5000

// Normalized bf16 descriptors (static device scratch — allocation-free)
__device__ __nv_bfloat16 g_q16[(size_t)NQTOT * C_];
__device__ __nv_bfloat16 g_s16[(size_t)NSTOT * C_];

__device__ __forceinline__ uint32_t smem_u32(const void* p) {
    uint32_t a;
    asm("{ .reg .u64 t; cvta.to.shared.u64 t, %1; cvt.u32.u64 %0, t; }"
        : "=r"(a) : "l"(p));
    return a;
}

#define SWZ128(o) ((o) ^ (((o) >> 3) & 0x70))

#define MBARRIER_INIT(addr, cnt) \
    asm volatile("mbarrier.init.shared.b64 [%0], %1;" \
        :: "r"((uint32_t)(addr)), "r"((uint32_t)(cnt)) : "memory")

#define MBARRIER_EXPECT_TX(addr, tx) \
    asm volatile("mbarrier.arrive.expect_tx.shared.b64 _, [%0], %1;" \
        :: "r"((uint32_t)(addr)), "r"((uint32_t)(tx)) : "memory")

#define MBARRIER_WAIT_PARITY(addr, par) do { \
    uint32_t _m = (uint32_t)(addr); uint32_t _p = (uint32_t)(par); uint32_t _d; \
    asm volatile("{ .reg .pred p; mbarrier.try_wait.parity.acquire.cta.shared::cta.b64 p, [%1], %2; selp.b32 %0, 1, 0, p; }" \
        : "=r"(_d) : "r"(_m), "r"(_p) : "memory"); \
    if (!_d) { \
        asm volatile("{ .reg .pred P1; WL_%=: mbarrier.try_wait.parity.acquire.cta.shared::cta.b64 P1, [%0], %1, 0x989680; @P1 bra.uni WD_%=; bra.uni WL_%=; WD_%=: }" \
            :: "r"(_m), "r"(_p) : "memory"); \
    } \
} while (0)

#define TMA3D(smaddr, tmap, cx, cy, cz, mb) \
    asm volatile("cp.async.bulk.tensor.3d.shared::cta.global.tile.mbarrier::complete_tx::bytes " \
        "[%0], [%1, {%2, %3, %4}], [%5];" \
        :: "r"((uint32_t)(smaddr)), "l"(tmap), "r"((int)(cx)), "r"((int)(cy)), \
           "r"((int)(cz)), "r"((uint32_t)(mb)) : "memory")

#define LDSM4(d, addr) \
    asm volatile("ldmatrix.sync.aligned.m8n8.x4.shared.b16 {%0,%1,%2,%3}, [%4];" \
        : "=r"((d)[0]), "=r"((d)[1]), "=r"((d)[2]), "=r"((d)[3]) : "r"(addr))

#define MMA16816(ac, a, b0, b1) \
    asm volatile("mma.sync.aligned.m16n8k16.row.col.f32.bf16.bf16.f32 " \
        "{%0,%1,%2,%3}, {%4,%5,%6,%7}, {%8,%9}, {%0,%1,%2,%3};" \
        : "+f"((ac)[0]), "+f"((ac)[1]), "+f"((ac)[2]), "+f"((ac)[3]) \
        : "r"((a)[0]), "r"((a)[1]), "r"((a)[2]), "r"((a)[3]), "r"(b0), "r"(b1))

// ---------------------------------------------------------------------------
// Kernel 1: L2-normalize each 640-dim descriptor, cast to bf16.
// One warp per row (20000 rows). Block 0 also zeroes the 750-float output.
// ---------------------------------------------------------------------------
__global__ void normalize_kernel(const float* __restrict__ q,
                                 const float* __restrict__ s,
                                 float* __restrict__ out) {
    if (blockIdx.x == 0 && threadIdx.x < 250) {
        #pragma unroll
        for (int j = 0; j < 3; j++) out[threadIdx.x + 250 * j] = 0.f;
    }

    int warp = (blockIdx.x * blockDim.x + threadIdx.x) >> 5;
    int lane = threadIdx.x & 31;
    if (warp >= NQTOT + NSTOT) return;

    const float* src;
    __nv_bfloat16* dst;
    if (warp < NQTOT) {
        src = q + (size_t)warp * C_;
        dst = g_q16 + (size_t)warp * C_;
    } else {
        int r = warp - NQTOT;
        src = s + (size_t)r * C_;
        dst = g_s16 + (size_t)r * C_;
    }

    const float4* p4 = (const float4*)src;
    float4 v[5];
    float acc = 0.f;
    #pragma unroll
    for (int t = 0; t < 5; t++) {
        v[t] = p4[lane + 32 * t];
        acc += v[t].x * v[t].x + v[t].y * v[t].y + v[t].z * v[t].z + v[t].w * v[t].w;
    }
    #pragma unroll
    for (int o = 16; o; o >>= 1) acc += __shfl_xor_sync(0xFFFFFFFFu, acc, o);
    float inv = rsqrtf(acc);

    #pragma unroll
    for (int t = 0; t < 5; t++) {
        __nv_bfloat162 lo = __float22bfloat162_rn(make_float2(v[t].x * inv, v[t].y * inv));
        __nv_bfloat162 hi = __float22bfloat162_rn(make_float2(v[t].z * inv, v[t].w * inv));
        uint2 pack;
        pack.x = *(uint32_t*)&lo;
        pack.y = *(uint32_t*)&hi;
        *(uint2*)(dst + (size_t)(lane + 32 * t) * 4) = pack;
    }
}

// ---------------------------------------------------------------------------
// Kernel 2: fused bf16 HMMA GEMM (128 x 512 x 640) + streaming top-5 + reduce.
// TMA loads, 3-buffer mbarrier pipeline, fine-grained LDSM/MMA interleave:
// each B-quad LDSM is prefetched one group ahead and hidden behind 4 MMAs.
// ---------------------------------------------------------------------------
#define BM   128
#define BNC  128           // N chunk
#define BK   64            // K chunk (64 bf16 = 128B rows, SW128)
#define NKC  (C_/BK)       // 10
#define NNC  4             // N chunks (covers 512 padded)
#define NSTG (NNC*NKC)     // 40 stages

#define STG_BYTES 32768
#define SMEM_TOTAL (3 * STG_BYTES + 1024 + 64)   // buffers + align pad + mbars

__global__ __launch_bounds__(256, 2)
void fused_gemm_topk_kernel(float* __restrict__ out,
                            const __grid_constant__ CUtensorMap tmA,
                            const __grid_constant__ CUtensorMap tmB) {
    extern __shared__ __align__(1024) char smem[];
    const uint32_t sb   = (smem_u32(smem) + 1023u) & ~1023u;  // 1024-aligned
    const uint32_t mbar = sb + 3 * STG_BYTES;                 // 3 mbarriers
    const int tid   = threadIdx.x;
    const int lane  = tid & 31;
    const int wid   = tid >> 5;
    const int warpM = wid >> 1;      // 0..3
    const int warpN = wid & 1;       // 0..1

    const int mBlock = blockIdx.x * BM;
    const int z   = blockIdx.y;      // b*5 + group
    const int b   = z / SHOT_;
    const int grp = z % SHOT_;

    // ---- mbarrier init + first two TMA loads ----
    if (tid == 0) {
        MBARRIER_INIT(mbar + 0,  1);
        MBARRIER_INIT(mbar + 8,  1);
        MBARRIER_INIT(mbar + 16, 1);
        asm volatile("fence.proxy.async.shared::cta;" ::: "memory");
    }
    __syncthreads();
    if (tid == 0) {
        MBARRIER_EXPECT_TX(mbar + 0, 2 * 16384);
        TMA3D(sb,                 &tmA, 0,  mBlock, b, mbar + 0);
        TMA3D(sb + 16384,         &tmB, 0,  0,      z, mbar + 0);
        MBARRIER_EXPECT_TX(mbar + 8, 2 * 16384);
        TMA3D(sb + STG_BYTES,         &tmA, 64, mBlock, b, mbar + 8);
        TMA3D(sb + STG_BYTES + 16384, &tmB, 64, 0,      z, mbar + 8);
    }

    // ---- ldmatrix bases (XOR with ks<<5 per step) ----
    uint32_t baseA[2], baseB[4];
    #pragma unroll
    for (int mt = 0; mt < 2; mt++) {
        int row = warpM * 32 + mt * 16 + (lane & 15);
        baseA[mt] = SWZ128((uint32_t)(row * 128 + (lane >> 4) * 16));
    }
    {
        int qd = lane >> 3, rr = lane & 7;
        #pragma unroll
        for (int nt2 = 0; nt2 < 4; nt2++) {
            int row = warpN * 64 + nt2 * 16 + (qd >> 1) * 8 + rr;
            baseB[nt2] = SWZ128((uint32_t)(row * 128 + (qd & 1) * 16));
        }
    }

    // running top-5 per owned row: rr -> row = warpM*32 + rr*8 + lane/4
    float t5[4][5];
    #pragma unroll
    for (int r = 0; r < 4; r++)
        #pragma unroll
        for (int j = 0; j < 5; j++) t5[r][j] = -INFINITY;

    float acc[2][8][4];
    #pragma unroll
    for (int mt = 0; mt < 2; mt++)
        #pragma unroll
        for (int nt = 0; nt < 8; nt++)
            #pragma unroll
            for (int c = 0; c < 4; c++) acc[mt][nt][c] = 0.f;

    // ---- compute one stage: rolling LDSM/MMA interleave ----
    auto compute_from = [&](const uint32_t bufoff) {
        const uint32_t sAb = sb + bufoff;
        const uint32_t sBb = sAb + 16384;
        uint32_t a[2][4], an[2][4];   // current / next-ks A frags
        uint32_t bc[4], bn[4];        // current / next B quad

        LDSM4(a[0], sAb + baseA[0]);
        LDSM4(a[1], sAb + baseA[1]);
        LDSM4(bc,   sBb + baseB[0]);

        #pragma unroll
        for (int ks = 0; ks < 4; ks++) {
            const uint32_t kx  = (uint32_t)(ks << 5);
            const uint32_t kxn = (uint32_t)((ks + 1) << 5);
            #pragma unroll
            for (int nt2 = 0; nt2 < 4; nt2++) {
                // prefetch next B quad (hidden behind the 4 MMAs below)
                if (nt2 < 3) {
                    LDSM4(bn, sBb + (baseB[nt2 + 1] ^ kx));
                } else if (ks < 3) {
                    LDSM4(bn, sBb + (baseB[0] ^ kxn));
                }
                // prefetch next-ks A frags mid-group
                if (nt2 == 1 && ks < 3) {
                    LDSM4(an[0], sAb + (baseA[0] ^ kxn));
                    LDSM4(an[1], sAb + (baseA[1] ^ kxn));
                }
                MMA16816(acc[0][nt2 * 2 + 0], a[0], bc[0], bc[1]);
                MMA16816(acc[0][nt2 * 2 + 1], a[0], bc[2], bc[3]);
                MMA16816(acc[1][nt2 * 2 + 0], a[1], bc[0], bc[1]);
                MMA16816(acc[1][nt2 * 2 + 1], a[1], bc[2], bc[3]);
                #pragma unroll
                for (int i = 0; i < 4; i++) bc[i] = bn[i];
            }
            #pragma unroll
            for (int mt = 0; mt < 2; mt++)
                #pragma unroll
                for (int i = 0; i < 4; i++) a[mt][i] = an[mt][i];
        }
    };

    int ckc = 0, ccb = 0;          // compute-side kc/cb counters
    auto fold_topk = [&](bool clip) {
        const int colBase = ccb * BNC + warpN * 64 + (lane & 3) * 2;
        #pragma unroll
        for (int mt = 0; mt < 2; mt++)
            #pragma unroll
            for (int c2 = 0; c2 < 2; c2++)
                #pragma unroll
                for (int nt = 0; nt < 8; nt++)
                    #pragma unroll
                    for (int c1 = 0; c1 < 2; c1++) {
                        float v = acc[mt][nt][c2 * 2 + c1];
                        bool ok = !clip || (colBase + nt * 8 + c1 < NROWS);
                        if (ok && v > t5[mt * 2 + c2][4]) {
                            t5[mt * 2 + c2][4] = v;
                            #pragma unroll
                            for (int j = 4; j > 0; j--) {
                                if (t5[mt * 2 + c2][j] > t5[mt * 2 + c2][j - 1]) {
                                    float x = t5[mt * 2 + c2][j];
                                    t5[mt * 2 + c2][j] = t5[mt * 2 + c2][j - 1];
                                    t5[mt * 2 + c2][j - 1] = x;
                                }
                            }
                        }
                    }
        #pragma unroll
        for (int mt = 0; mt < 2; mt++)
            #pragma unroll
            for (int nt = 0; nt < 8; nt++)
                #pragma unroll
                for (int c = 0; c < 4; c++) acc[mt][nt][c] = 0.f;
    };

    int s = 0;
    #define DO_STAGE(K, PH)                                                    \
        do {                                                                   \
            __syncthreads();                                                   \
            if (tid == 0 && s + 2 < NSTG) {                                    \
                const int ns = s + 2;                                          \
                const int nkc = ns % NKC, ncb = ns / NKC;                      \
                const uint32_t dbuf = sb + (((K) + 2) % 3) * STG_BYTES;        \
                const uint32_t nmb = mbar + (((K) + 2) % 3) * 8;               \
                MBARRIER_EXPECT_TX(nmb, 2 * 16384);                            \
                TMA3D(dbuf,         &tmA, nkc * 64, mBlock,    b, nmb);        \
                TMA3D(dbuf + 16384, &tmB, nkc * 64, ncb * 128, z, nmb);        \
            }                                                                  \
            MBARRIER_WAIT_PARITY(mbar + (K) * 8, (PH));                        \
            compute_from((K) * STG_BYTES);                                     \
            if (ckc == NKC - 1) { fold_topk(ccb == NNC - 1); ckc = 0; ccb++; } \
            else ckc++;                                                        \
            s++;                                                               \
        } while (0)

    #pragma unroll 1
    for (int t = 0; t < 13; t++) {      // stages 0..38
        const int ph = t & 1;
        DO_STAGE(0, ph);
        DO_STAGE(1, ph);
        DO_STAGE(2, ph);
    }
    DO_STAGE(0, 1);                     // stage 39 (buf0, 14th use -> parity 1)
    #undef DO_STAGE

    // dump per-thread top-5s: row x 8 contributors x 5 (20KB, reuses smem)
    __syncthreads();
    float* dump = (float*)smem;
    const int slot = warpN * 4 + (lane & 3);
    #pragma unroll
    for (int rr = 0; rr < 4; rr++) {
        int row = warpM * 32 + rr * 8 + (lane >> 2);
        #pragma unroll
        for (int j = 0; j < 5; j++)
            dump[row * 40 + slot * 5 + j] = t5[rr][j];
    }
    __syncthreads();

    // final: one thread per row merges 40 candidates -> top-5 mean -> atomicAdd
    if (tid < BM) {
        int gm = mBlock + tid;
        if (gm < MROWS) {
            const float* vals = dump + tid * 40;
            float s0 = -INFINITY, s1 = -INFINITY, s2 = -INFINITY,
                  s3 = -INFINITY, s4 = -INFINITY;
            #pragma unroll
            for (int i = 0; i < 40; i++) {
                float v = vals[i];
                if (v > s4) {
                    s4 = v;
                    if (s4 > s3) { float x = s4; s4 = s3; s3 = x; }
                    if (s3 > s2) { float x = s3; s3 = s2; s2 = x; }
                    if (s2 > s1) { float x = s2; s2 = s1; s1 = x; }
                    if (s1 > s0) { float x = s1; s1 = s0; s0 = x; }
                }
            }
            int q = gm / HW_;
            float val = (s0 + s1 + s2 + s3 + s4) * (1.0f / NK_);
            atomicAdd(&out[(b * Q_ + q) * WAY_ + grp], val);
        }
    }
}

// ---------------------------------------------------------------------------
// Host: build tensormaps (driver entry point fetched via runtime — no -lcuda)
// ---------------------------------------------------------------------------
typedef CUresult (*EncodeTiledFn)(
    CUtensorMap*, CUtensorMapDataType, cuuint32_t, void*,
    const cuuint64_t*, const cuuint64_t*, const cuuint32_t*, const cuuint32_t*,
    CUtensorMapInterleave, CUtensorMapSwizzle, CUtensorMapL2promotion,
    CUtensorMapFloatOOBfill);

extern "C" void kernel_launch(void* const* d_in, const int* in_sizes, int n_in,
                              void* d_out, int out_size) {
    const float* input1 = (const float*)d_in[0];   // [2,75,10,10,640]
    const float* input2 = (const float*)d_in[1];   // [2,5,5,10,10,640]
    float* out = (float*)d_out;                    // [2,75,5] = 750

    void* fn = nullptr;
    cudaDriverEntryPointQueryResult qres;
    cudaGetDriverEntryPoint("cuTensorMapEncodeTiled", &fn,
                            cudaEnableDefault, &qres);
    EncodeTiledFn encode = (EncodeTiledFn)fn;

    void *qptr = nullptr, *sptr = nullptr;
    cudaGetSymbolAddress(&qptr, g_q16);
    cudaGetSymbolAddress(&sptr, g_s16);

    CUtensorMap tmA, tmB;
    {   // A: [2][7500][640] bf16, box [64, 128, 1], SW128
        cuuint64_t dims[3]    = {C_, MROWS, B_};
        cuuint64_t strides[2] = {C_ * 2ull, (cuuint64_t)MROWS * C_ * 2ull};
        cuuint32_t box[3]     = {BK, BM, 1};
        cuuint32_t ones[3]    = {1, 1, 1};
        encode(&tmA, CU_TENSOR_MAP_DATA_TYPE_BFLOAT16, 3, qptr,
               dims, strides, box, ones,
               CU_TENSOR_MAP_INTERLEAVE_NONE, CU_TENSOR_MAP_SWIZZLE_128B,
               CU_TENSOR_MAP_L2_PROMOTION_L2_128B,
               CU_TENSOR_MAP_FLOAT_OOB_FILL_NONE);
    }
    {   // B: [10][500][640] bf16, box [64, 128, 1], SW128 (OOB rows -> 0)
        cuuint64_t dims[3]    = {C_, NROWS, NGRP};
        cuuint64_t strides[2] = {C_ * 2ull, (cuuint64_t)NROWS * C_ * 2ull};
        cuuint32_t box[3]     = {BK, BM, 1};
        cuuint32_t ones[3]    = {1, 1, 1};
        encode(&tmB, CU_TENSOR_MAP_DATA_TYPE_BFLOAT16, 3, sptr,
               dims, strides, box, ones,
               CU_TENSOR_MAP_INTERLEAVE_NONE, CU_TENSOR_MAP_SWIZZLE_128B,
               CU_TENSOR_MAP_L2_PROMOTION_L2_128B,
               CU_TENSOR_MAP_FLOAT_OOB_FILL_NONE);
    }

    cudaFuncSetAttribute(fused_gemm_topk_kernel,
                         cudaFuncAttributeMaxDynamicSharedMemorySize, SMEM_TOTAL);

    normalize_kernel<<<(NQTOT + NSTOT + 7) / 8, 256>>>(input1, input2, out);

    dim3 grid((MROWS + BM - 1) / BM, NGRP);        // (59, 10)
    fused_gemm_topk_kernel<<<grid, 256, SMEM_TOTAL>>>(out, tmA, tmB);
}